// round 1
// baseline (speedup 1.0000x reference)
#include <cuda_runtime.h>
#include <math.h>

#define BB   8
#define TT   150
#define DD   30
#define HH   5
#define HDD  6
#define LL   3
#define NI   40     // BB*HH
#define KL   300
#define KA   74
#define KV   35
#define AA   5      // a-values per attention block

// ---------------- device scratch (no allocations allowed) ----------------
__device__ float g_mod[3][TT*BB*DD];          // 0: pl, 1: pa, 2: pv   [T,B,D]
__device__ float g_h[2][TT*BB*DD];            // per-stream hidden state [T,B,D]
__device__ float g_K[2][LL][NI*TT*HDD];       // per (s,l): [i, t, e]
__device__ float g_V[2][LL][NI*TT*HDD];
__device__ float g_vbar[2][LL][NI*HDD];
__device__ float g_Q[2][NI*TT*HDD];           // current-layer Q
__device__ float g_attn[2][TT*BB*DD];         // attention output [T,B,D]

__device__ __forceinline__ float warpsum(float v){
    #pragma unroll
    for (int o=16;o>0;o>>=1) v += __shfl_xor_sync(0xffffffffu, v, o);
    return v;
}

// ---------------- 1. modality projections (conv1d k=1) -------------------
// pl/pa/pv[t,b,d] = sum_k x[b,t,k] * W[d,k]
__global__ void k_proj(const float* __restrict__ xl, const float* __restrict__ xa,
                       const float* __restrict__ xv, const float* __restrict__ Wl,
                       const float* __restrict__ Wa, const float* __restrict__ Wv){
    int r = blockIdx.x;          // 0..T*B-1
    int mod = blockIdx.y;        // 0,1,2
    int t = r / BB, b = r % BB;
    const float *x, *W; int K;
    if (mod==0){x=xl;W=Wl;K=KL;} else if (mod==1){x=xa;W=Wa;K=KA;} else {x=xv;W=Wv;K=KV;}
    __shared__ float sx[KL];
    const float* xr = x + (b*TT + t)*K;
    for (int k=threadIdx.x; k<K; k+=32) sx[k]=xr[k];
    __syncthreads();
    int d = threadIdx.x;
    if (d < DD){
        float acc = 0.f;
        const float* wr = W + d*K;
        for (int k=0;k<K;k++) acc = fmaf(sx[k], wr[k], acc);
        int o = (t*BB+b)*DD + d;
        g_mod[mod][o] = acc;
        if (mod==0){ g_h[0][o]=acc; g_h[1][o]=acc; }  // h starts as pl for both streams
    }
}

// ---------------- 2. precompute K,V for all (stream,layer) ---------------
__global__ void k_kv(const float* __restrict__ in_w, const float* __restrict__ in_b,
                     const float* __restrict__ n1g, const float* __restrict__ n1b){
    int idx = blockIdx.x;                 // 2*L*T*B blocks
    int b = idx % BB; idx /= BB;
    int t = idx % TT; idx /= TT;
    int l = idx % LL; int s = idx / LL;
    int ksrc = (s==0)?1:2, vsrc=(s==0)?2:1;   // s0: K<-pa,V<-pv ; s1: K<-pv,V<-pa
    __shared__ float sK[DD], sV[DD];
    int d = threadIdx.x;
    int ro = (t*BB+b)*DD;
    float kv = (d<DD)? g_mod[ksrc][ro+d] : 0.f;
    float vv = (d<DD)? g_mod[vsrc][ro+d] : 0.f;
    float ksum = warpsum(kv), ksq = warpsum(kv*kv);
    float vsum = warpsum(vv), vsq = warpsum(vv*vv);
    float km = ksum*(1.f/DD), kvar = ksq*(1.f/DD) - km*km;
    float vm = vsum*(1.f/DD), vvar = vsq*(1.f/DD) - vm*vm;
    float krs = rsqrtf(kvar+1e-5f), vrs = rsqrtf(vvar+1e-5f);
    int pb = (s*LL+l)*DD;
    if (d<DD){
        float g = n1g[pb+d], be = n1b[pb+d];
        sK[d] = (kv-km)*krs*g + be;
        sV[d] = (vv-vm)*vrs*g + be;
    }
    __syncthreads();
    if (d<DD){
        const float* iw = in_w + (s*LL+l)*3*DD*DD;
        const float* ib = in_b + (s*LL+l)*3*DD;
        float ka = ib[DD+d], va = ib[2*DD+d];
        const float* wk = iw + (DD+d)*DD;
        const float* wv = iw + (2*DD+d)*DD;
        #pragma unroll
        for (int j=0;j<DD;j++){ ka = fmaf(sK[j], wk[j], ka); va = fmaf(sV[j], wv[j], va); }
        int i = b*HH + d/HDD, e = d%HDD;
        int o = (i*TT + t)*HDD + e;
        g_K[s][l][o] = ka;
        g_V[s][l][o] = va;
    }
}

// ---------------- 2b. vbar = mean over t of V -----------------------------
__global__ void k_vbar(){
    int idx = blockIdx.x;                 // 2*L*NI blocks
    int i = idx % NI; idx /= NI;
    int l = idx % LL; int s = idx / LL;
    int e = threadIdx.x;
    if (e < HDD){
        float acc = 0.f;
        const float* v = g_V[s][l] + i*TT*HDD + e;
        for (int t=0;t<TT;t++) acc += v[t*HDD];
        g_vbar[s][l][i*HDD+e] = acc * (1.f/TT);
    }
}

// ---------------- 3. per-layer Q projection ------------------------------
__global__ void k_q(const float* __restrict__ in_w, const float* __restrict__ in_b,
                    const float* __restrict__ n1g, const float* __restrict__ n1b, int l){
    int idx = blockIdx.x;                 // 2*T*B blocks
    int b = idx % BB; idx /= BB;
    int t = idx % TT; int s = idx / TT;
    __shared__ float sX[DD];
    int d = threadIdx.x;
    int ro = (t*BB+b)*DD;
    float x = (d<DD)? g_h[s][ro+d] : 0.f;
    float sum = warpsum(x), sq = warpsum(x*x);
    float m = sum*(1.f/DD), var = sq*(1.f/DD)-m*m, r = rsqrtf(var+1e-5f);
    int pb = (s*LL+l)*DD;
    if (d<DD) sX[d] = (x-m)*r*n1g[pb+d] + n1b[pb+d];
    __syncthreads();
    if (d<DD){
        const float* iw = in_w + (s*LL+l)*3*DD*DD + d*DD;
        float acc = in_b[(s*LL+l)*3*DD + d];
        #pragma unroll
        for (int j=0;j<DD;j++) acc = fmaf(sX[j], iw[j], acc);
        acc *= 0.4082482904638631f;       // HD^-0.5
        int i = b*HH + d/HDD, e = d%HDD;
        g_Q[s][(i*TT+t)*HDD+e] = acc;
    }
}

// ---------------- 4. attention core (the hot kernel) ---------------------
// One block per (s, i, 5-a group). 160 threads, thread = one b (key index).
// fused[a,b] = (q_a o k_b) . vbar  +  max_c (q_a o k_b) . v_c
// then softmax over b and attn[a,:] = sum_b p_b * q_b  (note: q, per reference)
__global__ void __launch_bounds__(160) k_att(int l){
    int s = blockIdx.z, i = blockIdx.y, a0 = blockIdx.x*AA;
    int tid = threadIdx.x;
    __shared__ float4 sV4[TT*2];           // v padded to 8 floats per c
    __shared__ float  sQa[AA*HDD];
    __shared__ float  sVbar[HDD];
    __shared__ float  sred[5*8];
    const float* Kp = g_K[s][l] + i*TT*HDD;
    const float* Vp = g_V[s][l] + i*TT*HDD;
    const float* Qp = g_Q[s]    + i*TT*HDD;
    float* sVf = (float*)sV4;
    for (int j=tid; j<TT*8; j+=160) sVf[j] = 0.f;
    __syncthreads();
    for (int j=tid; j<TT*HDD; j+=160){ int c=j/HDD, e=j%HDD; sVf[c*8+e] = Vp[j]; }
    if (tid < AA*HDD) sQa[tid] = Qp[a0*HDD + tid];
    if (tid < HDD)    sVbar[tid] = g_vbar[s][l][i*HDD + tid];
    __syncthreads();

    bool valid = tid < TT;
    int b = valid ? tid : 0;
    float kb[HDD], qb[HDD];
    #pragma unroll
    for (int e=0;e<HDD;e++){ kb[e]=Kp[b*HDD+e]; qb[e]=Qp[b*HDD+e]; }

    float kq[AA][HDD], mean_[AA], mx[AA];
    #pragma unroll
    for (int a=0;a<AA;a++){
        float m = 0.f;
        #pragma unroll
        for (int e=0;e<HDD;e++){ kq[a][e] = sQa[a*HDD+e]*kb[e]; m = fmaf(kq[a][e], sVbar[e], m); }
        mean_[a] = m;
        mx[a] = -INFINITY;
    }

    #pragma unroll 2
    for (int c=0;c<TT;c++){
        float4 v0 = sV4[2*c], v1 = sV4[2*c+1];
        #pragma unroll
        for (int a=0;a<AA;a++){
            float sc = kq[a][0]*v0.x;
            sc = fmaf(kq[a][1], v0.y, sc);
            sc = fmaf(kq[a][2], v0.z, sc);
            sc = fmaf(kq[a][3], v0.w, sc);
            sc = fmaf(kq[a][4], v1.x, sc);
            sc = fmaf(kq[a][5], v1.y, sc);
            mx[a] = fmaxf(mx[a], sc);
        }
    }

    int b_ = i/HH, h_ = i%HH;
    #pragma unroll 1
    for (int a=0;a<AA;a++){
        float fused = valid ? (mean_[a] + mx[a]) : -INFINITY;
        // block max over b
        float m = fused;
        #pragma unroll
        for (int o=16;o>0;o>>=1) m = fmaxf(m, __shfl_xor_sync(0xffffffffu, m, o));
        if ((tid&31)==0) sred[tid>>5] = m;
        __syncthreads();
        m = fmaxf(fmaxf(sred[0],sred[1]), fmaxf(fmaxf(sred[2],sred[3]), sred[4]));
        __syncthreads();
        float ex = __expf(fused - m);      // invalid lanes: exp(-inf)=0
        float vals[7];
        #pragma unroll
        for (int e=0;e<HDD;e++) vals[e] = ex*qb[e];
        vals[6] = ex;
        #pragma unroll
        for (int j=0;j<7;j++){
            float v = vals[j];
            #pragma unroll
            for (int o=16;o>0;o>>=1) v += __shfl_xor_sync(0xffffffffu, v, o);
            if ((tid&31)==0) sred[(tid>>5)*8 + j] = v;
        }
        __syncthreads();
        if (tid < HDD){
            float num=0.f, den=0.f;
            #pragma unroll
            for (int w=0;w<5;w++){ num += sred[w*8+tid]; den += sred[w*8+6]; }
            g_attn[s][((a0+a)*BB + b_)*DD + h_*HDD + tid] = num/den;
        }
        __syncthreads();
    }
}

// ---------------- 5. out-proj + residual + LN + FFN + residual -----------
__global__ void k_ffn(const float* __restrict__ out_w, const float* __restrict__ out_b,
                      const float* __restrict__ w1, const float* __restrict__ b1,
                      const float* __restrict__ w2, const float* __restrict__ b2,
                      const float* __restrict__ n2g, const float* __restrict__ n2b, int l){
    int idx = blockIdx.x;                 // 2*T*B blocks
    int b = idx % BB; idx /= BB;
    int t = idx % TT; int s = idx / TT;
    int tid = threadIdx.x;
    __shared__ float sAttn[DD], sXn[DD], sHid[4*DD];
    int ro = (t*BB+b)*DD;
    if (tid<DD) sAttn[tid] = g_attn[s][ro+tid];
    __syncthreads();
    int pl_ = s*LL+l;
    float x = 0.f;
    if (tid<DD){
        const float* wr = out_w + pl_*DD*DD + tid*DD;
        float acc = out_b[pl_*DD + tid];
        #pragma unroll
        for (int j=0;j<DD;j++) acc = fmaf(sAttn[j], wr[j], acc);
        x = g_h[s][ro+tid] + acc;         // residual
    }
    float sum = warpsum(x), sq = warpsum(x*x);
    float m = sum*(1.f/DD), var = sq*(1.f/DD)-m*m, r = rsqrtf(var+1e-5f);
    if (tid<DD) sXn[tid] = (x-m)*r*n2g[pl_*DD+tid] + n2b[pl_*DD+tid];
    __syncthreads();
    for (int j=tid; j<4*DD; j+=32){
        const float* wr = w1 + pl_*4*DD*DD + j*DD;
        float acc = b1[pl_*4*DD + j];
        #pragma unroll
        for (int q=0;q<DD;q++) acc = fmaf(sXn[q], wr[q], acc);
        sHid[j] = fmaxf(acc, 0.f);
    }
    __syncthreads();
    if (tid<DD){
        const float* wr = w2 + pl_*DD*4*DD + tid*4*DD;
        float acc = b2[pl_*DD + tid];
        #pragma unroll 4
        for (int j=0;j<4*DD;j++) acc = fmaf(sHid[j], wr[j], acc);
        g_h[s][ro+tid] = x + acc;         // residual 2
    }
}

// ---------------- 6. head: concat last timestep, proj MLP, output --------
__global__ void k_head(const float* __restrict__ p1w, const float* __restrict__ p1b,
                       const float* __restrict__ p2w, const float* __restrict__ p2b,
                       const float* __restrict__ ow, const float* __restrict__ ob,
                       float* __restrict__ out){
    int tid = threadIdx.x;                // 64 threads
    __shared__ float sLast[BB*2*DD], sHid[2*DD], sC[2*DD];
    for (int idx=tid; idx<BB*2*DD; idx+=64){
        int b = idx/(2*DD), j = idx%(2*DD);
        float v = (j<DD) ? g_h[0][((TT-1)*BB+b)*DD + j]
                         : g_h[1][((TT-1)*BB+b)*DD + (j-DD)];
        sLast[idx] = v;
        out[BB + idx] = v;                // last_hs after out[0:8]
    }
    __syncthreads();
    for (int b=0;b<BB;b++){
        if (tid < 2*DD){
            float acc = p1b[tid];
            const float* wr = p1w + tid*2*DD;
            for (int j=0;j<2*DD;j++) acc = fmaf(sLast[b*2*DD+j], wr[j], acc);
            sHid[tid] = fmaxf(acc, 0.f);
        }
        __syncthreads();
        if (tid < 2*DD){
            float acc = p2b[tid];
            const float* wr = p2w + tid*2*DD;
            for (int j=0;j<2*DD;j++) acc = fmaf(sHid[j], wr[j], acc);
            acc += sLast[b*2*DD+tid];     // residual
            sC[tid] = acc * ow[tid];
        }
        __syncthreads();
        if (tid==0){
            float acc = ob[0];
            for (int j=0;j<2*DD;j++) acc += sC[j];
            out[b] = acc;
        }
        __syncthreads();
    }
}

// -------------------------------------------------------------------------
extern "C" void kernel_launch(void* const* d_in, const int* in_sizes, int n_in,
                              void* d_out, int out_size){
    const float* xl   = (const float*)d_in[0];
    const float* xa   = (const float*)d_in[1];
    const float* xv   = (const float*)d_in[2];
    const float* Wl   = (const float*)d_in[3];
    const float* Wa   = (const float*)d_in[4];
    const float* Wv   = (const float*)d_in[5];
    const float* in_w = (const float*)d_in[6];
    const float* in_b = (const float*)d_in[7];
    const float* outw = (const float*)d_in[8];
    const float* outb = (const float*)d_in[9];
    const float* l1w  = (const float*)d_in[10];
    const float* l1b  = (const float*)d_in[11];
    const float* l2w  = (const float*)d_in[12];
    const float* l2b  = (const float*)d_in[13];
    const float* n1g  = (const float*)d_in[14];
    const float* n1b  = (const float*)d_in[15];
    const float* n2g  = (const float*)d_in[16];
    const float* n2b  = (const float*)d_in[17];
    const float* p1w  = (const float*)d_in[18];
    const float* p1b  = (const float*)d_in[19];
    const float* p2w  = (const float*)d_in[20];
    const float* p2b  = (const float*)d_in[21];
    const float* ow   = (const float*)d_in[22];
    const float* ob   = (const float*)d_in[23];
    float* out = (float*)d_out;

    k_proj<<<dim3(TT*BB, 3), 32>>>(xl, xa, xv, Wl, Wa, Wv);
    k_kv<<<2*LL*TT*BB, 32>>>(in_w, in_b, n1g, n1b);
    k_vbar<<<2*LL*NI, 32>>>();
    for (int l=0; l<LL; l++){
        k_q<<<2*TT*BB, 32>>>(in_w, in_b, n1g, n1b, l);
        k_att<<<dim3(TT/AA, NI, 2), 160>>>(l);
        k_ffn<<<2*TT*BB, 32>>>(outw, outb, l1w, l1b, l2w, l2b, n2g, n2b, l);
    }
    k_head<<<1, 64>>>(p1w, p1b, p2w, p2b, ow, ob, out);
}